// round 14
// baseline (speedup 1.0000x reference)
#include <cuda_runtime.h>

#define D 128
#define TM 128          // gemm rows per block (512 threads)
#define N_NODES 100000
#define WDS 130         // shWd stride in pairs per k (128 + 2 pad)
#define ZS  132         // shZ stride in floats per k (128 + 4 pad)
#define SSTR 136        // staging stride in shorts per row

// Quantized operands for the edge phase (halved gather bytes):
__device__ short g_z16[N_NODES * D];    // z, int16 row-scaled   (25.6 MB)
__device__ short g_wz16[N_NODES * D];   // wz, int16 row-scaled  (25.6 MB)
__device__ float g_sz[N_NODES];         // per-row scale of z
__device__ float g_sw[N_NODES];         // per-row scale of wz
__device__ int   g_idx64;               // 1 if edge_index is int64

#define UNPACK2(lo, hi, in) \
    asm("mov.b64 {%0, %1}, %2;" : "=f"(lo), "=f"(hi) : "l"(in))
#define FMA2(acc, a, b) \
    asm("fma.rn.f32x2 %0, %1, %2, %0;" : "+l"(acc) : "l"(a), "l"(b))

// dp4a variants (mixed signedness for the int16 -> 2x int8 decomposition)
#define DP4A_SS(acc, a, b) \
    asm("dp4a.s32.s32 %0, %1, %2, %0;" : "+r"(acc) : "r"(a), "r"(b))
#define DP4A_SU(acc, a, b) \
    asm("dp4a.s32.u32 %0, %1, %2, %0;" : "+r"(acc) : "r"(a), "r"(b))
#define DP4A_US(acc, a, b) \
    asm("dp4a.u32.s32 %0, %1, %2, %0;" : "+r"(acc) : "r"(a), "r"(b))
#define DP4A_UU(acc, a, b) \
    asm("dp4a.u32.u32 %0, %1, %2, %0;" : "+r"(acc) : "r"(a), "r"(b))
#define PRMT(out, a, b, sel) \
    asm("prmt.b32 %0, %1, %2, %3;" : "=r"(out) : "r"(a), "r"(b), "n"(sel))

__device__ __forceinline__ short q15(float v, float inv) {
    int q = __float2int_rn(v * inv);
    q = max(-32767, min(32767, q));
    return (short)q;
}

__device__ __forceinline__ unsigned long long dup2(float v) {
    unsigned long long r;
    asm("mov.b64 %0, {%1, %1};" : "=l"(r) : "f"(v));
    return r;
}

// ---------------------------------------------------------------------------
// z quantization: one warp per row (butterfly row-max, int15 scale).
// Block 0 thread 0 also detects edge_index width (int64 samples all lie in
// [0,N); int32 read as int64 packs two indices and only looks valid when the
// high half is 0, p~1e-5/sample; 64 samples -> certain). Deterministic.
// Runs as a parallel graph branch alongside the GEMM (disjoint outputs).
// ---------------------------------------------------------------------------
__global__ void __launch_bounds__(256) zquant_kernel(const float* __restrict__ z,
                                                     const long long* __restrict__ ei64,
                                                     int E, int n_rows) {
    if (blockIdx.x == 0 && threadIdx.x == 0) {
        int all_valid = 1;
        const int step = E > 64 ? E / 64 : 1;
        for (int i = 0; i < 64; i++) {
            long long v = ei64[(long long)(i * step) % E];
            if (v < 0 || v >= N_NODES) { all_valid = 0; break; }
        }
        g_idx64 = all_valid;
    }

    const int row = (int)((blockIdx.x * 256u + threadIdx.x) >> 5);
    const int lane = threadIdx.x & 31;
    if (row >= n_rows) return;

    const float4 v = ((const float4*)(z + (size_t)row * D))[lane];
    float m = fmaxf(fmaxf(fabsf(v.x), fabsf(v.y)), fmaxf(fabsf(v.z), fabsf(v.w)));
    #pragma unroll
    for (int off = 16; off > 0; off >>= 1)
        m = fmaxf(m, __shfl_xor_sync(0xffffffffu, m, off));

    const float inv = 32767.0f / fmaxf(m, 1e-30f);
    short4 q;
    q.x = q15(v.x, inv); q.y = q15(v.y, inv);
    q.z = q15(v.z, inv); q.w = q15(v.w, inv);
    ((short4*)(g_z16 + (size_t)row * D))[lane] = q;
    if (lane == 0) g_sz[row] = m * (1.0f / 32767.0f);
}

// ---------------------------------------------------------------------------
// GEMM, pack-free form: wz[n][o] = sum_k z[n][k]*W[o][k] + b[o].
// W stored DUPLICATED in smem: shWd[k][c] = (w,w) as one 8-byte element, so
// the row-pair FFMA2 inner loop has ZERO mov.b64 packs:
//   per k/thread: 4x LDS.64 (w-dup, lane-consecutive -> conflict-free)
//               + 2x LDS.128 (z row-pairs, warp-broadcast) + 16 FFMA2.
// 512 threads, 128 rows x 128 cols per block; thread tile 8 rows x 4 STRIDED
// cols (c = lane + {0,32,64,96}). smem: Wdup 133.1 KB + shZ 67.6 KB = 200.7KB
// -> 1 block/SM, 16 warps. Epilogue quantizes rows to int16 and stages the
// shorts through (now-free) smem for coalesced short4 stores.
// ---------------------------------------------------------------------------
__global__ void __launch_bounds__(512, 1) gemm_kernel(const float* __restrict__ z,
                                                      const float* __restrict__ W,
                                                      const float* __restrict__ b,
                                                      int n_rows) {
    extern __shared__ unsigned long long shd[];
    unsigned long long* shWd = shd;                     // [128][WDS] pairs
    float* shZ = (float*)(shd + D * WDS);               // [128][ZS] floats

    const int t = threadIdx.x;
    const int row0 = blockIdx.x * TM;

    // W-dup fill: gmem coalesced (consecutive k); one-time STS conflicts ok.
    #pragma unroll 8
    for (int i = 0; i < D * D / 512; i++) {
        const int idx = t + i * 512;
        const int k = idx & 127, o = idx >> 7;
        shWd[k * WDS + o] = dup2(W[o * D + k]);
    }
    // Z fill (transposing to k-major): gmem coalesced.
    #pragma unroll 8
    for (int i = 0; i < TM * D / 512; i++) {
        const int idx = t + i * 512;
        const int k = idx & 127, r = idx >> 7;
        int row = row0 + r; if (row >= n_rows) row = n_rows - 1;
        shZ[k * ZS + r] = z[(size_t)row * D + k];
    }
    __syncthreads();

    const int lane = t & 31;
    const int wrp = t >> 5;          // 0..15
    const int r0 = wrp * 8;          // 8 rows per warp

    unsigned long long acc2[4][4];   // [row_pair][strided col j]
    #pragma unroll
    for (int rp = 0; rp < 4; rp++)
        #pragma unroll
        for (int c = 0; c < 4; c++) acc2[rp][c] = 0ull;

    #pragma unroll 4
    for (int k = 0; k < D; k++) {
        const unsigned long long* wrow = &shWd[k * WDS];
        const unsigned long long wd0 = wrow[lane];
        const unsigned long long wd1 = wrow[lane + 32];
        const unsigned long long wd2 = wrow[lane + 64];
        const unsigned long long wd3 = wrow[lane + 96];

        const ulonglong2 zA = *(const ulonglong2*)&shZ[k * ZS + r0];
        const ulonglong2 zB = *(const ulonglong2*)&shZ[k * ZS + r0 + 4];
        const unsigned long long zp[4] = {zA.x, zA.y, zB.x, zB.y};

        #pragma unroll
        for (int rp = 0; rp < 4; rp++) {
            FMA2(acc2[rp][0], zp[rp], wd0);
            FMA2(acc2[rp][1], zp[rp], wd1);
            FMA2(acc2[rp][2], zp[rp], wd2);
            FMA2(acc2[rp][3], zp[rp], wd3);
        }
    }

    // Epilogue: bias, per-row warp max (lanes cover all 128 cols), quantize,
    // stage shorts in smem, then coalesced short4 stores.
    float bb[4];
    #pragma unroll
    for (int j = 0; j < 4; j++) bb[j] = b[lane + 32 * j];

    float vals[8][4];
    #pragma unroll
    for (int rp = 0; rp < 4; rp++) {
        #pragma unroll
        for (int j = 0; j < 4; j++) {
            float lo, hi;
            UNPACK2(lo, hi, acc2[rp][j]);
            vals[2 * rp][j]     = lo + bb[j];
            vals[2 * rp + 1][j] = hi + bb[j];
        }
    }

    __syncthreads();                       // main-loop smem reads complete
    short* shS = (short*)shd;              // staging [TM][SSTR] shorts (34.8KB)

    #pragma unroll
    for (int r = 0; r < 8; r++) {
        float m = fmaxf(fmaxf(fabsf(vals[r][0]), fabsf(vals[r][1])),
                        fmaxf(fabsf(vals[r][2]), fabsf(vals[r][3])));
        #pragma unroll
        for (int off = 16; off > 0; off >>= 1)
            m = fmaxf(m, __shfl_xor_sync(0xffffffffu, m, off));

        const float inv = 32767.0f / fmaxf(m, 1e-30f);
        const int rloc = r0 + r;
        #pragma unroll
        for (int j = 0; j < 4; j++)
            shS[rloc * SSTR + lane + 32 * j] = q15(vals[r][j], inv);

        const int row = row0 + rloc;
        if (lane == 0 && row < n_rows)
            g_sw[row] = m * (1.0f / 32767.0f);
    }
    __syncthreads();

    // Coalesced store: 128 rows x 32 short4 per row = 4096 short4.
    #pragma unroll
    for (int i = 0; i < TM * (D / 4) / 512; i++) {
        const int idx = t + i * 512;
        const int c4 = idx & 31, r = idx >> 5;
        const int row = row0 + r;
        if (row < n_rows) {
            const short4 q = *(const short4*)&shS[r * SSTR + c4 * 4];
            *(short4*)&g_wz16[(size_t)row * D + c4 * 4] = q;
        }
    }
}

// ---------------------------------------------------------------------------
// Edge compute: out[e] = sigmoid( sz[src]*sw[dst] * dot(z16[src], wz16[dst]) )
// 8 lanes per edge, 4 edges per warp; lane loads its 32 B segment as 2x
// LDG.128. int16 dot via int8 decomposition:
//   a*b = 65536*ah*bh + 256*(ah*bl + al*bh) + al*bl
// PRMT splits hi(signed)/lo(unsigned) byte planes, 4 dp4a chains, exact
// integer partials, one fp32 combine per lane, 3-level butterfly.
// ---------------------------------------------------------------------------
__global__ void __launch_bounds__(512) edge_kernel(const void* __restrict__ ei_raw,
                                                   float* __restrict__ out,
                                                   int E) {
    const int warp = (int)((blockIdx.x * 512u + threadIdx.x) >> 5);
    const int lane = threadIdx.x & 31;
    const int sub  = lane >> 3;
    const int off  = lane & 7;

    long long e = (long long)warp * 4 + sub;
    const long long e_clamped = e < E ? e : (long long)E - 1;

    int src, dst;
    if (g_idx64) {
        const long long* ei = (const long long*)ei_raw;
        src = (int)ei[e_clamped];
        dst = (int)ei[(long long)E + e_clamped];
    } else {
        const int* ei = (const int*)ei_raw;
        src = ei[e_clamped];
        dst = ei[E + e_clamped];
    }

    const float sc = g_sz[src] * g_sw[dst];

    const int4* za = (const int4*)(g_z16 + (size_t)src * D);
    const int4* wa = (const int4*)(g_wz16 + (size_t)dst * D);
    const int4 a0 = za[2 * off];
    const int4 a1 = za[2 * off + 1];
    const int4 w0 = wa[2 * off];
    const int4 w1 = wa[2 * off + 1];

    const int areg[8] = {a0.x, a0.y, a0.z, a0.w, a1.x, a1.y, a1.z, a1.w};
    const int wreg[8] = {w0.x, w0.y, w0.z, w0.w, w1.x, w1.y, w1.z, w1.w};

    int hh = 0, hl = 0, lh = 0, ll = 0;
    #pragma unroll
    for (int p = 0; p < 4; p++) {
        int ah, al, bh, bl;
        PRMT(ah, areg[2 * p], areg[2 * p + 1], 0x7531);
        PRMT(al, areg[2 * p], areg[2 * p + 1], 0x6420);
        PRMT(bh, wreg[2 * p], wreg[2 * p + 1], 0x7531);
        PRMT(bl, wreg[2 * p], wreg[2 * p + 1], 0x6420);
        DP4A_SS(hh, ah, bh);
        DP4A_SU(hl, ah, bl);
        DP4A_US(lh, al, bh);
        DP4A_UU(ll, al, bl);
    }

    float s = 65536.0f * (float)hh;
    s = fmaf(256.0f, (float)(hl + lh), s);
    s += (float)ll;

    s += __shfl_xor_sync(0xffffffffu, s, 4);
    s += __shfl_xor_sync(0xffffffffu, s, 2);
    s += __shfl_xor_sync(0xffffffffu, s, 1);

    if (off == 0 && e < E)
        out[e] = 1.0f / (1.0f + __expf(-s * sc));
}

// ---------------------------------------------------------------------------
// Launch with a parallel graph branch (zquant alongside gemm), join at edge.
// ---------------------------------------------------------------------------
extern "C" void kernel_launch(void* const* d_in, const int* in_sizes, int n_in,
                              void* d_out, int out_size) {
    const float* z  = (const float*)d_in[0];
    const void*  ei = d_in[1];
    const float* W  = (const float*)d_in[2];
    const float* b  = (const float*)d_in[3];
    float* out = (float*)d_out;

    const int E = out_size;
    const int n_rows = in_sizes[0] / D;

    cudaStream_t s2;
    cudaStreamCreateWithFlags(&s2, cudaStreamNonBlocking);
    cudaEvent_t ev_fork, ev_join;
    cudaEventCreateWithFlags(&ev_fork, cudaEventDisableTiming);
    cudaEventCreateWithFlags(&ev_join, cudaEventDisableTiming);

    cudaEventRecord(ev_fork, 0);
    cudaStreamWaitEvent(s2, ev_fork, 0);

    zquant_kernel<<<(n_rows * 32 + 255) / 256, 256, 0, s2>>>(
        z, (const long long*)ei, E, n_rows);
    cudaEventRecord(ev_join, s2);

    const int smem = D * WDS * 8 + D * ZS * 4;          // 200704 B
    cudaFuncSetAttribute(gemm_kernel, cudaFuncAttributeMaxDynamicSharedMemorySize, smem);
    gemm_kernel<<<(n_rows + TM - 1) / TM, 512, smem>>>(z, W, b, n_rows);

    cudaStreamWaitEvent(0, ev_join, 0);

    const int warps_needed = (E + 3) / 4;
    const int blocks = (warps_needed + 15) / 16;
    edge_kernel<<<blocks, 512>>>(ei, out, E);

    cudaEventDestroy(ev_fork);
    cudaEventDestroy(ev_join);
    cudaStreamDestroy(s2);
}

// round 16
// speedup vs baseline: 1.5145x; 1.5145x over previous
#include <cuda_runtime.h>
#include <cuda_bf16.h>
#include <cstdint>

#define D 128
#define N_NODES 100000

__device__ short g_z16[N_NODES * D];
__device__ short g_wz16[N_NODES * D];
__device__ float g_sz[N_NODES];
__device__ float g_sw[N_NODES];
__device__ int   g_idx64;

// ---- dp4a / prmt (edge kernel) ----
#define DP4A_SS(acc, a, b) asm("dp4a.s32.s32 %0, %1, %2, %0;" : "+r"(acc) : "r"(a), "r"(b))
#define DP4A_SU(acc, a, b) asm("dp4a.s32.u32 %0, %1, %2, %0;" : "+r"(acc) : "r"(a), "r"(b))
#define DP4A_US(acc, a, b) asm("dp4a.u32.s32 %0, %1, %2, %0;" : "+r"(acc) : "r"(a), "r"(b))
#define DP4A_UU(acc, a, b) asm("dp4a.u32.u32 %0, %1, %2, %0;" : "+r"(acc) : "r"(a), "r"(b))
#define PRMT(out, a, b, sel) asm("prmt.b32 %0, %1, %2, %3;" : "=r"(out) : "r"(a), "r"(b), "n"(sel))

// ---- ldmatrix / mma.sync (sm_80+ features, valid on plain sm_103) ----
#define LDMATRIX_X4(r0, r1, r2, r3, addr) \
    asm volatile("ldmatrix.sync.aligned.m8n8.x4.shared.b16 {%0,%1,%2,%3}, [%4];" \
                 : "=r"(r0), "=r"(r1), "=r"(r2), "=r"(r3) : "r"(addr))
#define MMA_BF16(c, a0, a1, a2, a3, b0, b1) \
    asm volatile("mma.sync.aligned.m16n8k16.row.col.f32.bf16.bf16.f32 " \
                 "{%0,%1,%2,%3}, {%4,%5,%6,%7}, {%8,%9}, {%0,%1,%2,%3};" \
                 : "+f"((c)[0]), "+f"((c)[1]), "+f"((c)[2]), "+f"((c)[3]) \
                 : "r"(a0), "r"(a1), "r"(a2), "r"(a3), "r"(b0), "r"(b1))

__device__ __forceinline__ uint32_t smem_to_u32(const void* p) {
    uint32_t a;
    asm("{ .reg .u64 t; cvta.to.shared.u64 t, %1; cvt.u32.u64 %0, t; }" : "=r"(a) : "l"(p));
    return a;
}

__device__ __forceinline__ short q15(float v, float inv) {
    int q = __float2int_rn(v * inv);
    q = max(-32767, min(32767, q));
    return (short)q;
}

// smem layout (bytes). bf16 tiles 128 rows x 136 cols (272 B row stride).
#define RSTR   272
#define TILE_B 34816
#define SM_BIAS 0
#define SM_AH   512
#define SM_AL   (SM_AH + TILE_B)
#define SM_BH   (SM_AL + TILE_B)
#define SM_BL   (SM_BH + TILE_B)
#define SM_TOTAL (SM_BL + TILE_B)      // 139776 B

// ---------------------------------------------------------------------------
// z quantization (+ edge_index dtype detect); parallel graph branch.
// ---------------------------------------------------------------------------
__global__ void __launch_bounds__(256) zquant_kernel(const float* __restrict__ z,
                                                     const long long* __restrict__ ei64,
                                                     int E, int n_rows) {
    if (blockIdx.x == 0 && threadIdx.x == 0) {
        int all_valid = 1;
        const int step = E > 64 ? E / 64 : 1;
        for (int i = 0; i < 64; i++) {
            long long v = ei64[(long long)(i * step) % E];
            if (v < 0 || v >= N_NODES) { all_valid = 0; break; }
        }
        g_idx64 = all_valid;
    }
    const int row = (int)((blockIdx.x * 256u + threadIdx.x) >> 5);
    const int lane = threadIdx.x & 31;
    if (row >= n_rows) return;

    const float4 v = ((const float4*)(z + (size_t)row * D))[lane];
    float m = fmaxf(fmaxf(fabsf(v.x), fabsf(v.y)), fmaxf(fabsf(v.z), fabsf(v.w)));
    #pragma unroll
    for (int off = 16; off > 0; off >>= 1)
        m = fmaxf(m, __shfl_xor_sync(0xffffffffu, m, off));

    const float inv = 32767.0f / fmaxf(m, 1e-30f);
    short4 q;
    q.x = q15(v.x, inv); q.y = q15(v.y, inv);
    q.z = q15(v.z, inv); q.w = q15(v.w, inv);
    ((short4*)(g_z16 + (size_t)row * D))[lane] = q;
    if (lane == 0) g_sz[row] = m * (1.0f / 32767.0f);
}

// ---------------------------------------------------------------------------
// bf16-split tensor GEMM via mma.sync: wz = z @ W^T + b, int16 output.
// Block 256 thr (8 warps), tile 128 rows x 128 cols. Warp w owns rows
// 16w..16w+15 (all 128 cols): per k-chunk of 16, 2x ldmatrix.x4 for A
// (hi, lo) + per n-tile one FUSED ldmatrix.x4 (Bh matrices 0,1 + Bl 0,1)
// + 3 MMAs (AhBh, AhBl, AlBh). C frag: 16 n-tiles x 4 f32 regs.
// Epilogue: bias in-reg, row-max over the 4 lanes holding each row
// (shfl_xor 1,2), quantize -> smem staging (reuse Bh) -> coalesced short4.
// ---------------------------------------------------------------------------
__global__ void __launch_bounds__(256, 1) gemm_mma_kernel(const float* __restrict__ z,
                                                          const float* __restrict__ W,
                                                          const float* __restrict__ b,
                                                          int n_rows) {
    extern __shared__ char smem[];
    const uint32_t sb = smem_to_u32(smem);
    const int t = threadIdx.x;
    const int wid = t >> 5, lane = t & 31;
    const int row0 = blockIdx.x * 128;

    if (t < 128) *(float*)(smem + SM_BIAS + t * 4) = b[t];

    // Fill + split-convert: 128x32 float4 items each for A(z) and B(W).
    #pragma unroll 4
    for (int i = 0; i < 16; i++) {
        const int idx = t + i * 256;
        const int r = idx >> 5, c4 = idx & 31;
        const uint32_t off = (uint32_t)(r * RSTR + c4 * 8);
        {
            int grow = row0 + r; if (grow >= n_rows) grow = n_rows - 1;
            const float4 v = ((const float4*)(z + (size_t)grow * D))[c4];
            __nv_bfloat16 h0 = __float2bfloat16(v.x), h1 = __float2bfloat16(v.y);
            __nv_bfloat16 h2 = __float2bfloat16(v.z), h3 = __float2bfloat16(v.w);
            ushort4 qh = {__bfloat16_as_ushort(h0), __bfloat16_as_ushort(h1),
                          __bfloat16_as_ushort(h2), __bfloat16_as_ushort(h3)};
            ushort4 ql = {
                __bfloat16_as_ushort(__float2bfloat16(v.x - __bfloat162float(h0))),
                __bfloat16_as_ushort(__float2bfloat16(v.y - __bfloat162float(h1))),
                __bfloat16_as_ushort(__float2bfloat16(v.z - __bfloat162float(h2))),
                __bfloat16_as_ushort(__float2bfloat16(v.w - __bfloat162float(h3)))};
            *(ushort4*)(smem + SM_AH + off) = qh;
            *(ushort4*)(smem + SM_AL + off) = ql;
        }
        {
            const float4 v = ((const float4*)(W + (size_t)r * D))[c4];
            __nv_bfloat16 h0 = __float2bfloat16(v.x), h1 = __float2bfloat16(v.y);
            __nv_bfloat16 h2 = __float2bfloat16(v.z), h3 = __float2bfloat16(v.w);
            ushort4 qh = {__bfloat16_as_ushort(h0), __bfloat16_as_ushort(h1),
                          __bfloat16_as_ushort(h2), __bfloat16_as_ushort(h3)};
            ushort4 ql = {
                __bfloat16_as_ushort(__float2bfloat16(v.x - __bfloat162float(h0))),
                __bfloat16_as_ushort(__float2bfloat16(v.y - __bfloat162float(h1))),
                __bfloat16_as_ushort(__float2bfloat16(v.z - __bfloat162float(h2))),
                __bfloat16_as_ushort(__float2bfloat16(v.w - __bfloat162float(h3)))};
            *(ushort4*)(smem + SM_BH + off) = qh;
            *(ushort4*)(smem + SM_BL + off) = ql;
        }
    }
    __syncthreads();

    const int warp_r0 = wid * 16;
    const int tr = lane & 7;         // row within 8-group
    const int sel = lane >> 3;       // ldmatrix matrix selector (0..3)

    // A addresses: matrices {r0-7 k0-7, r8-15 k0-7, r0-7 k8-15, r8-15 k8-15}
    const uint32_t a_row = (uint32_t)((warp_r0 + tr + (sel & 1) * 8) * RSTR
                                      + (sel >> 1) * 16);
    const uint32_t aH = sb + SM_AH + a_row;
    const uint32_t aL = sb + SM_AL + a_row;
    // Fused B x4: matrices {Bh k0-7, Bh k8-15, Bl k0-7, Bl k8-15}
    const uint32_t b_addr0 = sb + ((sel & 2) ? SM_BL : SM_BH)
                             + (uint32_t)(tr * RSTR + (sel & 1) * 16);

    float c[16][4];
    #pragma unroll
    for (int nt = 0; nt < 16; nt++)
        #pragma unroll
        for (int j = 0; j < 4; j++) c[nt][j] = 0.0f;

    #pragma unroll
    for (int kc = 0; kc < 8; kc++) {
        uint32_t ah0, ah1, ah2, ah3, al0, al1, al2, al3;
        LDMATRIX_X4(ah0, ah1, ah2, ah3, aH + kc * 32);
        LDMATRIX_X4(al0, al1, al2, al3, aL + kc * 32);
        #pragma unroll
        for (int nt = 0; nt < 16; nt++) {
            uint32_t bh0, bh1, bl0, bl1;
            LDMATRIX_X4(bh0, bh1, bl0, bl1, b_addr0 + nt * (8 * RSTR) + kc * 32);
            MMA_BF16(c[nt], ah0, ah1, ah2, ah3, bh0, bh1);
            MMA_BF16(c[nt], ah0, ah1, ah2, ah3, bl0, bl1);
            MMA_BF16(c[nt], al0, al1, al2, al3, bh0, bh1);
        }
    }

    // Epilogue: bias add; C frag: c0,c1 -> row warp_r0+lane/4, cols
    // nt*8+(lane%4)*2+{0,1}; c2,c3 -> row +8.
    const float* bias = (const float*)(smem + SM_BIAS);
    const int q4 = lane & 3;
    #pragma unroll
    for (int nt = 0; nt < 16; nt++) {
        const float b0 = bias[nt * 8 + q4 * 2];
        const float b1 = bias[nt * 8 + q4 * 2 + 1];
        c[nt][0] += b0; c[nt][1] += b1;
        c[nt][2] += b0; c[nt][3] += b1;
    }

    float mlo = 0.0f, mhi = 0.0f;
    #pragma unroll
    for (int nt = 0; nt < 16; nt++) {
        mlo = fmaxf(mlo, fmaxf(fabsf(c[nt][0]), fabsf(c[nt][1])));
        mhi = fmaxf(mhi, fmaxf(fabsf(c[nt][2]), fabsf(c[nt][3])));
    }
    mlo = fmaxf(mlo, __shfl_xor_sync(0xffffffffu, mlo, 1));
    mlo = fmaxf(mlo, __shfl_xor_sync(0xffffffffu, mlo, 2));
    mhi = fmaxf(mhi, __shfl_xor_sync(0xffffffffu, mhi, 1));
    mhi = fmaxf(mhi, __shfl_xor_sync(0xffffffffu, mhi, 2));

    const float invlo = 32767.0f / fmaxf(mlo, 1e-30f);
    const float invhi = 32767.0f / fmaxf(mhi, 1e-30f);

    const int rlo = warp_r0 + (lane >> 2);
    const int rhi = rlo + 8;
    if (q4 == 0) {
        if (row0 + rlo < n_rows) g_sw[row0 + rlo] = mlo * (1.0f / 32767.0f);
        if (row0 + rhi < n_rows) g_sw[row0 + rhi] = mhi * (1.0f / 32767.0f);
    }

    __syncthreads();                      // all mma smem reads done
    short* shS = (short*)(smem + SM_BH);  // staging [128][136] shorts
    #pragma unroll
    for (int nt = 0; nt < 16; nt++) {
        short2 qlo, qhi;
        qlo.x = q15(c[nt][0], invlo); qlo.y = q15(c[nt][1], invlo);
        qhi.x = q15(c[nt][2], invhi); qhi.y = q15(c[nt][3], invhi);
        *(short2*)&shS[rlo * 136 + nt * 8 + q4 * 2] = qlo;
        *(short2*)&shS[rhi * 136 + nt * 8 + q4 * 2] = qhi;
    }
    __syncthreads();

    // Coalesced short4 stores: 128 rows x 32 short4.
    #pragma unroll 4
    for (int i = 0; i < 16; i++) {
        const int idx = t + i * 256;
        const int r = idx >> 5, c4 = idx & 31;
        const int row = row0 + r;
        if (row < n_rows)
            *(short4*)&g_wz16[(size_t)row * D + c4 * 4] =
                *(const short4*)&shS[r * 136 + c4 * 4];
    }
}

// ---------------------------------------------------------------------------
// Edge compute (unchanged; ~81 us near its L2 byte floor).
// ---------------------------------------------------------------------------
__global__ void __launch_bounds__(512) edge_kernel(const void* __restrict__ ei_raw,
                                                   float* __restrict__ out,
                                                   int E) {
    const int warp = (int)((blockIdx.x * 512u + threadIdx.x) >> 5);
    const int lane = threadIdx.x & 31;
    const int sub  = lane >> 3;
    const int off  = lane & 7;

    long long e = (long long)warp * 4 + sub;
    const long long e_clamped = e < E ? e : (long long)E - 1;

    int src, dst;
    if (g_idx64) {
        const long long* ei = (const long long*)ei_raw;
        src = (int)ei[e_clamped];
        dst = (int)ei[(long long)E + e_clamped];
    } else {
        const int* ei = (const int*)ei_raw;
        src = ei[e_clamped];
        dst = ei[E + e_clamped];
    }

    const float sc = g_sz[src] * g_sw[dst];

    const int4* za = (const int4*)(g_z16 + (size_t)src * D);
    const int4* wa = (const int4*)(g_wz16 + (size_t)dst * D);
    const int4 a0 = za[2 * off];
    const int4 a1 = za[2 * off + 1];
    const int4 w0 = wa[2 * off];
    const int4 w1 = wa[2 * off + 1];

    const int areg[8] = {a0.x, a0.y, a0.z, a0.w, a1.x, a1.y, a1.z, a1.w};
    const int wreg[8] = {w0.x, w0.y, w0.z, w0.w, w1.x, w1.y, w1.z, w1.w};

    int hh = 0, hl = 0, lh = 0, ll = 0;
    #pragma unroll
    for (int p = 0; p < 4; p++) {
        int ah, al, bh, bl;
        PRMT(ah, areg[2 * p], areg[2 * p + 1], 0x7531);
        PRMT(al, areg[2 * p], areg[2 * p + 1], 0x6420);
        PRMT(bh, wreg[2 * p], wreg[2 * p + 1], 0x7531);
        PRMT(bl, wreg[2 * p], wreg[2 * p + 1], 0x6420);
        DP4A_SS(hh, ah, bh);
        DP4A_SU(hl, ah, bl);
        DP4A_US(lh, al, bh);
        DP4A_UU(ll, al, bl);
    }

    float s = 65536.0f * (float)hh;
    s = fmaf(256.0f, (float)(hl + lh), s);
    s += (float)ll;

    s += __shfl_xor_sync(0xffffffffu, s, 4);
    s += __shfl_xor_sync(0xffffffffu, s, 2);
    s += __shfl_xor_sync(0xffffffffu, s, 1);

    if (off == 0 && e < E)
        out[e] = 1.0f / (1.0f + __expf(-s * sc));
}

// ---------------------------------------------------------------------------
// Launch: zquant forked alongside the MMA GEMM; edge joins both.
// ---------------------------------------------------------------------------
extern "C" void kernel_launch(void* const* d_in, const int* in_sizes, int n_in,
                              void* d_out, int out_size) {
    const float* z  = (const float*)d_in[0];
    const void*  ei = d_in[1];
    const float* W  = (const float*)d_in[2];
    const float* b  = (const float*)d_in[3];
    float* out = (float*)d_out;

    const int E = out_size;
    const int n_rows = in_sizes[0] / D;

    cudaStream_t s2;
    cudaStreamCreateWithFlags(&s2, cudaStreamNonBlocking);
    cudaEvent_t ev_fork, ev_join;
    cudaEventCreateWithFlags(&ev_fork, cudaEventDisableTiming);
    cudaEventCreateWithFlags(&ev_join, cudaEventDisableTiming);

    cudaEventRecord(ev_fork, 0);
    cudaStreamWaitEvent(s2, ev_fork, 0);
    zquant_kernel<<<(n_rows * 32 + 255) / 256, 256, 0, s2>>>(
        z, (const long long*)ei, E, n_rows);
    cudaEventRecord(ev_join, s2);

    cudaFuncSetAttribute(gemm_mma_kernel, cudaFuncAttributeMaxDynamicSharedMemorySize,
                         SM_TOTAL);
    gemm_mma_kernel<<<(n_rows + 127) / 128, 256, SM_TOTAL>>>(z, W, b, n_rows);

    cudaStreamWaitEvent(0, ev_join, 0);

    const int warps_needed = (E + 3) / 4;
    const int blocks = (warps_needed + 15) / 16;
    edge_kernel<<<blocks, 512>>>(ei, out, E);

    cudaEventDestroy(ev_fork);
    cudaEventDestroy(ev_join);
    cudaStreamDestroy(s2);
}

// round 17
// speedup vs baseline: 1.5332x; 1.0124x over previous
#include <cuda_runtime.h>
#include <cuda_bf16.h>
#include <cstdint>

#define D 128
#define N_NODES 100000

__device__ short g_z16[N_NODES * D];
__device__ short g_wz16[N_NODES * D];
__device__ float g_sz[N_NODES];
__device__ float g_sw[N_NODES];
__device__ int   g_idx64;

// ---- dp4a / prmt (edge kernel) ----
#define DP4A_SS(acc, a, b) asm("dp4a.s32.s32 %0, %1, %2, %0;" : "+r"(acc) : "r"(a), "r"(b))
#define DP4A_SU(acc, a, b) asm("dp4a.s32.u32 %0, %1, %2, %0;" : "+r"(acc) : "r"(a), "r"(b))
#define DP4A_US(acc, a, b) asm("dp4a.u32.s32 %0, %1, %2, %0;" : "+r"(acc) : "r"(a), "r"(b))
#define DP4A_UU(acc, a, b) asm("dp4a.u32.u32 %0, %1, %2, %0;" : "+r"(acc) : "r"(a), "r"(b))
#define PRMT(out, a, b, sel) asm("prmt.b32 %0, %1, %2, %3;" : "=r"(out) : "r"(a), "r"(b), "n"(sel))

// ---- ldmatrix / mma.sync (sm_80+ features, valid on plain sm_103) ----
#define LDMATRIX_X4(r0, r1, r2, r3, addr) \
    asm volatile("ldmatrix.sync.aligned.m8n8.x4.shared.b16 {%0,%1,%2,%3}, [%4];" \
                 : "=r"(r0), "=r"(r1), "=r"(r2), "=r"(r3) : "r"(addr))
#define MMA_BF16(c, a0, a1, a2, a3, b0, b1) \
    asm volatile("mma.sync.aligned.m16n8k16.row.col.f32.bf16.bf16.f32 " \
                 "{%0,%1,%2,%3}, {%4,%5,%6,%7}, {%8,%9}, {%0,%1,%2,%3};" \
                 : "+f"((c)[0]), "+f"((c)[1]), "+f"((c)[2]), "+f"((c)[3]) \
                 : "r"(a0), "r"(a1), "r"(a2), "r"(a3), "r"(b0), "r"(b1))

__device__ __forceinline__ uint32_t smem_to_u32(const void* p) {
    uint32_t a;
    asm("{ .reg .u64 t; cvta.to.shared.u64 t, %1; cvt.u32.u64 %0, t; }" : "=r"(a) : "l"(p));
    return a;
}

__device__ __forceinline__ short q15(float v, float inv) {
    int q = __float2int_rn(v * inv);
    q = max(-32767, min(32767, q));
    return (short)q;
}

// smem layout (bytes). bf16 tiles 128 rows x 136 cols (272 B row stride).
#define RSTR   272
#define TILE_B 34816
#define SM_BIAS 0
#define SM_PMAX 512                     // float[2][128] partial row maxima
#define SM_AH   1536
#define SM_AL   (SM_AH + TILE_B)
#define SM_BH   (SM_AL + TILE_B)
#define SM_BL   (SM_BH + TILE_B)
#define SM_TOTAL (SM_BL + TILE_B)       // 140800 B

// ---------------------------------------------------------------------------
// z quantization (+ edge_index dtype detect); parallel graph branch.
// ---------------------------------------------------------------------------
__global__ void __launch_bounds__(256) zquant_kernel(const float* __restrict__ z,
                                                     const long long* __restrict__ ei64,
                                                     int E, int n_rows) {
    if (blockIdx.x == 0 && threadIdx.x == 0) {
        int all_valid = 1;
        const int step = E > 64 ? E / 64 : 1;
        for (int i = 0; i < 64; i++) {
            long long v = ei64[(long long)(i * step) % E];
            if (v < 0 || v >= N_NODES) { all_valid = 0; break; }
        }
        g_idx64 = all_valid;
    }
    const int row = (int)((blockIdx.x * 256u + threadIdx.x) >> 5);
    const int lane = threadIdx.x & 31;
    if (row >= n_rows) return;

    const float4 v = ((const float4*)(z + (size_t)row * D))[lane];
    float m = fmaxf(fmaxf(fabsf(v.x), fabsf(v.y)), fmaxf(fabsf(v.z), fabsf(v.w)));
    #pragma unroll
    for (int off = 16; off > 0; off >>= 1)
        m = fmaxf(m, __shfl_xor_sync(0xffffffffu, m, off));

    const float inv = 32767.0f / fmaxf(m, 1e-30f);
    short4 q;
    q.x = q15(v.x, inv); q.y = q15(v.y, inv);
    q.z = q15(v.z, inv); q.w = q15(v.w, inv);
    ((short4*)(g_z16 + (size_t)row * D))[lane] = q;
    if (lane == 0) g_sz[row] = m * (1.0f / 32767.0f);
}

// ---------------------------------------------------------------------------
// bf16-split tensor GEMM via mma.sync: wz = z @ W^T + b, int16 output.
// 512 threads (16 warps), tile 128 rows x 128 cols. Warp pair (w, w+8) owns
// rows 16w..16w+15; warp w computes n-tiles 0-7, warp w+8 n-tiles 8-15
// (4 warps/SMSP -> double latency hiding vs 8-warp version; same MMA total).
// Per k-chunk of 16: 2x ldmatrix.x4 for A (hi,lo) + per nt one FUSED
// ldmatrix.x4 (Bh m0,m1 + Bl m0,m1) + 3 MMAs (AhBh, AhBl, AlBh).
// Row max combined across the pair via smem pmax[2][128]; identical scale in
// both halves -> deterministic. Staging reuses the Bh region after the sync.
// ---------------------------------------------------------------------------
__global__ void __launch_bounds__(512, 1) gemm_mma_kernel(const float* __restrict__ z,
                                                          const float* __restrict__ W,
                                                          const float* __restrict__ b,
                                                          int n_rows) {
    extern __shared__ char smem[];
    const uint32_t sb = smem_to_u32(smem);
    const int t = threadIdx.x;
    const int wid = t >> 5, lane = t & 31;
    const int row0 = blockIdx.x * 128;

    if (t < 128) *(float*)(smem + SM_BIAS + t * 4) = b[t];

    // Fill + split-convert: 128x32 float4 items each for A(z) and B(W).
    #pragma unroll 4
    for (int i = 0; i < 8; i++) {
        const int idx = t + i * 512;
        const int r = idx >> 5, c4 = idx & 31;
        const uint32_t off = (uint32_t)(r * RSTR + c4 * 8);
        {
            int grow = row0 + r; if (grow >= n_rows) grow = n_rows - 1;
            const float4 v = ((const float4*)(z + (size_t)grow * D))[c4];
            __nv_bfloat16 h0 = __float2bfloat16(v.x), h1 = __float2bfloat16(v.y);
            __nv_bfloat16 h2 = __float2bfloat16(v.z), h3 = __float2bfloat16(v.w);
            ushort4 qh = {__bfloat16_as_ushort(h0), __bfloat16_as_ushort(h1),
                          __bfloat16_as_ushort(h2), __bfloat16_as_ushort(h3)};
            ushort4 ql = {
                __bfloat16_as_ushort(__float2bfloat16(v.x - __bfloat162float(h0))),
                __bfloat16_as_ushort(__float2bfloat16(v.y - __bfloat162float(h1))),
                __bfloat16_as_ushort(__float2bfloat16(v.z - __bfloat162float(h2))),
                __bfloat16_as_ushort(__float2bfloat16(v.w - __bfloat162float(h3)))};
            *(ushort4*)(smem + SM_AH + off) = qh;
            *(ushort4*)(smem + SM_AL + off) = ql;
        }
        {
            const float4 v = ((const float4*)(W + (size_t)r * D))[c4];
            __nv_bfloat16 h0 = __float2bfloat16(v.x), h1 = __float2bfloat16(v.y);
            __nv_bfloat16 h2 = __float2bfloat16(v.z), h3 = __float2bfloat16(v.w);
            ushort4 qh = {__bfloat16_as_ushort(h0), __bfloat16_as_ushort(h1),
                          __bfloat16_as_ushort(h2), __bfloat16_as_ushort(h3)};
            ushort4 ql = {
                __bfloat16_as_ushort(__float2bfloat16(v.x - __bfloat162float(h0))),
                __bfloat16_as_ushort(__float2bfloat16(v.y - __bfloat162float(h1))),
                __bfloat16_as_ushort(__float2bfloat16(v.z - __bfloat162float(h2))),
                __bfloat16_as_ushort(__float2bfloat16(v.w - __bfloat162float(h3)))};
            *(ushort4*)(smem + SM_BH + off) = qh;
            *(ushort4*)(smem + SM_BL + off) = ql;
        }
    }
    __syncthreads();

    const int pair = wid & 7;            // row group
    const int half = wid >> 3;           // nt half (0: nt 0-7, 1: nt 8-15)
    const int warp_r0 = pair * 16;
    const int nt_base = half * 8;
    const int tr = lane & 7;
    const int sel = lane >> 3;

    const uint32_t a_row = (uint32_t)((warp_r0 + tr + (sel & 1) * 8) * RSTR
                                      + (sel >> 1) * 16);
    const uint32_t aH = sb + SM_AH + a_row;
    const uint32_t aL = sb + SM_AL + a_row;
    const uint32_t b_addr0 = sb + ((sel & 2) ? SM_BL : SM_BH)
                             + (uint32_t)((nt_base * 8 + tr) * RSTR + (sel & 1) * 16);

    float c[8][4];
    #pragma unroll
    for (int nt = 0; nt < 8; nt++)
        #pragma unroll
        for (int j = 0; j < 4; j++) c[nt][j] = 0.0f;

    #pragma unroll
    for (int kc = 0; kc < 8; kc++) {
        uint32_t ah0, ah1, ah2, ah3, al0, al1, al2, al3;
        LDMATRIX_X4(ah0, ah1, ah2, ah3, aH + kc * 32);
        LDMATRIX_X4(al0, al1, al2, al3, aL + kc * 32);
        #pragma unroll
        for (int nt = 0; nt < 8; nt++) {
            uint32_t bh0, bh1, bl0, bl1;
            LDMATRIX_X4(bh0, bh1, bl0, bl1, b_addr0 + nt * (8 * RSTR) + kc * 32);
            MMA_BF16(c[nt], ah0, ah1, ah2, ah3, bh0, bh1);
            MMA_BF16(c[nt], ah0, ah1, ah2, ah3, bl0, bl1);
            MMA_BF16(c[nt], al0, al1, al2, al3, bh0, bh1);
        }
    }

    // Bias add. C frag: c0,c1 -> row warp_r0+lane/4, col (nt_base+nt)*8 +
    // (lane%4)*2 + {0,1}; c2,c3 -> row +8.
    const float* bias = (const float*)(smem + SM_BIAS);
    const int q4 = lane & 3;
    #pragma unroll
    for (int nt = 0; nt < 8; nt++) {
        const float b0 = bias[(nt_base + nt) * 8 + q4 * 2];
        const float b1 = bias[(nt_base + nt) * 8 + q4 * 2 + 1];
        c[nt][0] += b0; c[nt][1] += b1;
        c[nt][2] += b0; c[nt][3] += b1;
    }

    // Partial row max within this nt-half; butterfly -> all quad lanes.
    float mlo = 0.0f, mhi = 0.0f;
    #pragma unroll
    for (int nt = 0; nt < 8; nt++) {
        mlo = fmaxf(mlo, fmaxf(fabsf(c[nt][0]), fabsf(c[nt][1])));
        mhi = fmaxf(mhi, fmaxf(fabsf(c[nt][2]), fabsf(c[nt][3])));
    }
    mlo = fmaxf(mlo, __shfl_xor_sync(0xffffffffu, mlo, 1));
    mlo = fmaxf(mlo, __shfl_xor_sync(0xffffffffu, mlo, 2));
    mhi = fmaxf(mhi, __shfl_xor_sync(0xffffffffu, mhi, 1));
    mhi = fmaxf(mhi, __shfl_xor_sync(0xffffffffu, mhi, 2));

    const int rlo = warp_r0 + (lane >> 2);
    const int rhi = rlo + 8;
    float* pmax = (float*)(smem + SM_PMAX);     // [2][128]
    if (q4 == 0) {
        pmax[half * 128 + rlo] = mlo;
        pmax[half * 128 + rhi] = mhi;
    }
    __syncthreads();    // pmax visible; all mma smem reads complete

    const float Mlo = fmaxf(pmax[rlo], pmax[128 + rlo]);
    const float Mhi = fmaxf(pmax[rhi], pmax[128 + rhi]);
    const float invlo = 32767.0f / fmaxf(Mlo, 1e-30f);
    const float invhi = 32767.0f / fmaxf(Mhi, 1e-30f);

    if (q4 == 0 && half == 0) {
        if (row0 + rlo < n_rows) g_sw[row0 + rlo] = Mlo * (1.0f / 32767.0f);
        if (row0 + rhi < n_rows) g_sw[row0 + rhi] = Mhi * (1.0f / 32767.0f);
    }

    short* shS = (short*)(smem + SM_BH);        // staging [128][136] shorts
    #pragma unroll
    for (int nt = 0; nt < 8; nt++) {
        short2 qlo, qhi;
        qlo.x = q15(c[nt][0], invlo); qlo.y = q15(c[nt][1], invlo);
        qhi.x = q15(c[nt][2], invhi); qhi.y = q15(c[nt][3], invhi);
        *(short2*)&shS[rlo * 136 + (nt_base + nt) * 8 + q4 * 2] = qlo;
        *(short2*)&shS[rhi * 136 + (nt_base + nt) * 8 + q4 * 2] = qhi;
    }
    __syncthreads();

    // Coalesced short4 stores: 128 rows x 32 short4.
    #pragma unroll 4
    for (int i = 0; i < 8; i++) {
        const int idx = t + i * 512;
        const int r = idx >> 5, c4 = idx & 31;
        const int row = row0 + r;
        if (row < n_rows)
            *(short4*)&g_wz16[(size_t)row * D + c4 * 4] =
                *(const short4*)&shS[r * 136 + c4 * 4];
    }
}

// ---------------------------------------------------------------------------
// Edge compute (unchanged; ~81 us near its L1/L2 floor).
// ---------------------------------------------------------------------------
__global__ void __launch_bounds__(512) edge_kernel(const void* __restrict__ ei_raw,
                                                   float* __restrict__ out,
                                                   int E) {
    const int warp = (int)((blockIdx.x * 512u + threadIdx.x) >> 5);
    const int lane = threadIdx.x & 31;
    const int sub  = lane >> 3;
    const int off  = lane & 7;

    long long e = (long long)warp * 4 + sub;
    const long long e_clamped = e < E ? e : (long long)E - 1;

    int src, dst;
    if (g_idx64) {
        const long long* ei = (const long long*)ei_raw;
        src = (int)ei[e_clamped];
        dst = (int)ei[(long long)E + e_clamped];
    } else {
        const int* ei = (const int*)ei_raw;
        src = ei[e_clamped];
        dst = ei[E + e_clamped];
    }

    const float sc = g_sz[src] * g_sw[dst];

    const int4* za = (const int4*)(g_z16 + (size_t)src * D);
    const int4* wa = (const int4*)(g_wz16 + (size_t)dst * D);
    const int4 a0 = za[2 * off];
    const int4 a1 = za[2 * off + 1];
    const int4 w0 = wa[2 * off];
    const int4 w1 = wa[2 * off + 1];

    const int areg[8] = {a0.x, a0.y, a0.z, a0.w, a1.x, a1.y, a1.z, a1.w};
    const int wreg[8] = {w0.x, w0.y, w0.z, w0.w, w1.x, w1.y, w1.z, w1.w};

    int hh = 0, hl = 0, lh = 0, ll = 0;
    #pragma unroll
    for (int p = 0; p < 4; p++) {
        int ah, al, bh, bl;
        PRMT(ah, areg[2 * p], areg[2 * p + 1], 0x7531);
        PRMT(al, areg[2 * p], areg[2 * p + 1], 0x6420);
        PRMT(bh, wreg[2 * p], wreg[2 * p + 1], 0x7531);
        PRMT(bl, wreg[2 * p], wreg[2 * p + 1], 0x6420);
        DP4A_SS(hh, ah, bh);
        DP4A_SU(hl, ah, bl);
        DP4A_US(lh, al, bh);
        DP4A_UU(ll, al, bl);
    }

    float s = 65536.0f * (float)hh;
    s = fmaf(256.0f, (float)(hl + lh), s);
    s += (float)ll;

    s += __shfl_xor_sync(0xffffffffu, s, 4);
    s += __shfl_xor_sync(0xffffffffu, s, 2);
    s += __shfl_xor_sync(0xffffffffu, s, 1);

    if (off == 0 && e < E)
        out[e] = 1.0f / (1.0f + __expf(-s * sc));
}

// ---------------------------------------------------------------------------
// Launch: zquant forked alongside the MMA GEMM; edge joins both.
// ---------------------------------------------------------------------------
extern "C" void kernel_launch(void* const* d_in, const int* in_sizes, int n_in,
                              void* d_out, int out_size) {
    const float* z  = (const float*)d_in[0];
    const void*  ei = d_in[1];
    const float* W  = (const float*)d_in[2];
    const float* b  = (const float*)d_in[3];
    float* out = (float*)d_out;

    const int E = out_size;
    const int n_rows = in_sizes[0] / D;

    cudaStream_t s2;
    cudaStreamCreateWithFlags(&s2, cudaStreamNonBlocking);
    cudaEvent_t ev_fork, ev_join;
    cudaEventCreateWithFlags(&ev_fork, cudaEventDisableTiming);
    cudaEventCreateWithFlags(&ev_join, cudaEventDisableTiming);

    cudaEventRecord(ev_fork, 0);
    cudaStreamWaitEvent(s2, ev_fork, 0);
    zquant_kernel<<<(n_rows * 32 + 255) / 256, 256, 0, s2>>>(
        z, (const long long*)ei, E, n_rows);
    cudaEventRecord(ev_join, s2);

    cudaFuncSetAttribute(gemm_mma_kernel, cudaFuncAttributeMaxDynamicSharedMemorySize,
                         SM_TOTAL);
    gemm_mma_kernel<<<(n_rows + 127) / 128, 512, SM_TOTAL>>>(z, W, b, n_rows);

    cudaStreamWaitEvent(0, ev_join, 0);

    const int warps_needed = (E + 3) / 4;
    const int blocks = (warps_needed + 15) / 16;
    edge_kernel<<<blocks, 512>>>(ei, out, E);

    cudaEventDestroy(ev_fork);
    cudaEventDestroy(ev_join);
    cudaStreamDestroy(s2);
}